// round 1
// baseline (speedup 1.0000x reference)
#include <cuda_runtime.h>
#include <math_constants.h>

// Problem constants
static constexpr int Bsz = 8192;
static constexpr int S   = 30;
static constexpr int D   = 512;
static constexpr int H   = 1024;
static constexpr int K   = 1536;   // 3*D

// Scratch for the fused feature tensor [Bsz, 3D] (static __device__, no alloc)
__device__ float g_feat[(size_t)Bsz * K];

// ---------------------------------------------------------------------------
// Kernel 1: feature extraction.
// One thread per (b, d). Reads emb[b, s, d] for s=0..29 (coalesced across d),
// computes:
//   vl = max over s=0..27 of  conv3(x, w_long) at s
//   vm = max over s=23..27 of conv3(x, w_mid)  at s   (the "-7:" window)
//   vs = x[29]
// ---------------------------------------------------------------------------
__global__ __launch_bounds__(256) void feature_kernel(
    const float* __restrict__ emb,
    const float* __restrict__ wl,
    const float* __restrict__ wm,
    float* __restrict__ feat)
{
    int t = blockIdx.x * blockDim.x + threadIdx.x;   // 0 .. Bsz*D-1
    int b = t >> 9;          // / 512
    int d = t & (D - 1);     // % 512

    const float* p = emb + (size_t)b * (S * D) + d;

    float wl0 = wl[0], wl1 = wl[1], wl2 = wl[2];
    float wm0 = wm[0], wm1 = wm[1], wm2 = wm[2];

    float x0 = p[0];
    float x1 = p[D];
    float vl = -CUDART_INF_F;
    float vm = -CUDART_INF_F;

#pragma unroll
    for (int s = 0; s < 28; ++s) {
        float x2 = p[(s + 2) * D];
        float c = fmaf(x0, wl0, fmaf(x1, wl1, x2 * wl2));
        vl = fmaxf(vl, c);
        if (s >= 23) {
            float cm = fmaf(x0, wm0, fmaf(x1, wm1, x2 * wm2));
            vm = fmaxf(vm, cm);
        }
        x0 = x1;
        x1 = x2;
    }
    float vs = x1;  // x[29]

    float* f = feat + (size_t)b * K;
    f[d]         = vl;
    f[D + d]     = vm;
    f[2 * D + d] = vs;
}

// ---------------------------------------------------------------------------
// Packed f32x2 helpers (Blackwell): fma.rn.f32x2 does 2 fp32 FMAs per fma-pipe
// slot, halving fma-pipe pressure vs scalar FFMA.
// ---------------------------------------------------------------------------
__device__ __forceinline__ unsigned long long pack2(float x, float y) {
    unsigned long long r;
    asm("mov.b64 %0, {%1, %2};" : "=l"(r) : "f"(x), "f"(y));
    return r;
}
__device__ __forceinline__ void unpack2(unsigned long long v, float& x, float& y) {
    asm("mov.b64 {%0, %1}, %2;" : "=f"(x), "=f"(y) : "l"(v));
}
__device__ __forceinline__ void ffma2(unsigned long long& c,
                                      unsigned long long a,
                                      unsigned long long b) {
    asm("fma.rn.f32x2 %0, %1, %2, %0;" : "+l"(c) : "l"(a), "l"(b));
}

// ---------------------------------------------------------------------------
// Kernel 2: fused GEMM + tanh + W2 reduction.
//   hidden[b,h] = tanh( sum_k feat[b,k] * W1[h,k] )
//   out[b]     += sum_h hidden[b,h] * W2[h]        (atomic partial per block)
//
// Tiling: BM=64 rows x BN=64 hidden cols per block, BK=16, 256 threads,
// 4x4 per-thread micro-tile with m-paired f32x2 accumulators.
// B-tile uses a 16B-chunk XOR swizzle so the per-k LDS.128 of the b-fragment
// is 2-phase instead of 8-phase (keeps the smem crossbar off the critical path).
// ---------------------------------------------------------------------------
#define BM 64
#define BN 64
#define BK 16

__global__ __launch_bounds__(256) void gemm_tanh_kernel(
    const float* __restrict__ feat,
    const float* __restrict__ W1,
    const float* __restrict__ W2,
    float* __restrict__ out)
{
    __shared__ float As[BK][BM];   // As[kk][m]  (transposed A tile)
    __shared__ float Bs[BK][BN];   // Bs[kk][n]  (transposed W1 tile, swizzled chunks)

    const int tx = threadIdx.x;          // 0..255
    const int m0 = blockIdx.x * BM;
    const int n0 = blockIdx.y * BN;

    const int i = tx >> 4;   // 0..15  -> m block of 4 rows
    const int j = tx & 15;   // 0..15  -> n block of 4 cols

    // Global load mapping: one float4 along K per (row, quarter)
    const int lm = tx >> 2;          // 0..63 : tile row (m for A, n for B)
    const int lk = (tx & 3) << 2;    // 0,4,8,12

    const float* aG = feat + (size_t)(m0 + lm) * K + lk;
    const float* bG = W1   + (size_t)(n0 + lm) * K + lk;

    unsigned long long acc[2][4];    // [m-pair][n], each holds (m_even, m_odd)
#pragma unroll
    for (int p = 0; p < 2; ++p)
#pragma unroll
        for (int n = 0; n < 4; ++n) acc[p][n] = 0ULL;

    for (int k0 = 0; k0 < K; k0 += BK) {
        float4 av = *(const float4*)(aG + k0);
        float4 bv = *(const float4*)(bG + k0);

        __syncthreads();   // previous compute done before overwriting smem

        As[lk + 0][lm] = av.x;
        As[lk + 1][lm] = av.y;
        As[lk + 2][lm] = av.z;
        As[lk + 3][lm] = av.w;

        // Swizzled B store: logical chunk c = lm>>2 at row r goes to physical
        // chunk (c ^ (r&7)). Element offset within chunk preserved.
        {
            int c  = lm >> 2;
            int e  = lm & 3;
            float bb[4] = {bv.x, bv.y, bv.z, bv.w};
#pragma unroll
            for (int q = 0; q < 4; ++q) {
                int r = lk + q;
                Bs[r][((c ^ (r & 7)) << 2) + e] = bb[q];
            }
        }

        __syncthreads();

#pragma unroll
        for (int kk = 0; kk < BK; ++kk) {
            float4 a4 = *(const float4*)&As[kk][i << 2];
            float4 b4 = *(const float4*)&Bs[kk][((j ^ (kk & 7)) << 2)];

            unsigned long long ap0 = pack2(a4.x, a4.y);
            unsigned long long ap1 = pack2(a4.z, a4.w);
            unsigned long long bd0 = pack2(b4.x, b4.x);
            unsigned long long bd1 = pack2(b4.y, b4.y);
            unsigned long long bd2 = pack2(b4.z, b4.z);
            unsigned long long bd3 = pack2(b4.w, b4.w);

            ffma2(acc[0][0], ap0, bd0);
            ffma2(acc[1][0], ap1, bd0);
            ffma2(acc[0][1], ap0, bd1);
            ffma2(acc[1][1], ap1, bd1);
            ffma2(acc[0][2], ap0, bd2);
            ffma2(acc[1][2], ap1, bd2);
            ffma2(acc[0][3], ap0, bd3);
            ffma2(acc[1][3], ap1, bd3);
        }
    }

    // Epilogue: tanh + W2 weighting, reduce across the 16 j-threads per row.
    float w2v[4];
#pragma unroll
    for (int n = 0; n < 4; ++n) w2v[n] = W2[n0 + (j << 2) + n];

    float part[4] = {0.f, 0.f, 0.f, 0.f};   // rows m0 + i*4 + {0,1,2,3}
#pragma unroll
    for (int p = 0; p < 2; ++p) {
#pragma unroll
        for (int n = 0; n < 4; ++n) {
            float x, y;
            unpack2(acc[p][n], x, y);
            part[p * 2 + 0] += tanhf(x) * w2v[n];
            part[p * 2 + 1] += tanhf(y) * w2v[n];
        }
    }

    // Butterfly reduce over j (lanes: lane = (i&1)*16 + j, offsets 1..8 stay
    // within the 16-lane half that shares the same i / same rows).
#pragma unroll
    for (int off = 8; off > 0; off >>= 1) {
#pragma unroll
        for (int t = 0; t < 4; ++t)
            part[t] += __shfl_xor_sync(0xFFFFFFFFu, part[t], off);
    }

    if (j == 0) {
#pragma unroll
        for (int t = 0; t < 4; ++t)
            atomicAdd(&out[m0 + (i << 2) + t], part[t]);
    }
}

// ---------------------------------------------------------------------------
// Launch
// ---------------------------------------------------------------------------
extern "C" void kernel_launch(void* const* d_in, const int* in_sizes, int n_in,
                              void* d_out, int out_size)
{
    const float* emb    = (const float*)d_in[0];  // [8192, 30, 512]
    const float* w_long = (const float*)d_in[1];  // [3]
    const float* w_mid  = (const float*)d_in[2];  // [3]
    const float* W1     = (const float*)d_in[3];  // [1024, 1536]
    const float* W2     = (const float*)d_in[4];  // [1, 1024]
    float* out = (float*)d_out;                   // [8192]

    float* feat = nullptr;
    cudaGetSymbolAddress((void**)&feat, g_feat);

    // out is accumulated with atomics -> zero it (capturable memset node)
    cudaMemsetAsync(out, 0, (size_t)Bsz * sizeof(float));

    // Stage 1: features
    {
        int threads = 256;
        int blocks = (Bsz * D) / threads;   // 16384
        feature_kernel<<<blocks, threads>>>(emb, w_long, w_mid, feat);
    }

    // Stage 2: fused GEMM + tanh + W2 reduction
    {
        dim3 grid(Bsz / BM, H / BN);        // (128, 16)
        gemm_tanh_kernel<<<grid, 256>>>(feat, W1, W2, out);
    }
}

// round 2
// speedup vs baseline: 1.2122x; 1.2122x over previous
#include <cuda_runtime.h>
#include <math_constants.h>

// Problem constants
static constexpr int Bsz = 8192;
static constexpr int S   = 30;
static constexpr int D   = 512;
static constexpr int H   = 1024;
static constexpr int K   = 1536;   // 3*D

// Scratch for the fused feature tensor [Bsz, 3D]
__device__ float g_feat[(size_t)Bsz * K];

// ---------------------------------------------------------------------------
// Kernel 1: feature extraction (memory-bound streaming pass, ~80us, near floor)
// ---------------------------------------------------------------------------
__global__ __launch_bounds__(256) void feature_kernel(
    const float* __restrict__ emb,
    const float* __restrict__ wl,
    const float* __restrict__ wm,
    float* __restrict__ feat)
{
    int t = blockIdx.x * blockDim.x + threadIdx.x;   // 0 .. Bsz*D-1
    int b = t >> 9;          // / 512
    int d = t & (D - 1);     // % 512

    const float* p = emb + (size_t)b * (S * D) + d;

    float wl0 = wl[0], wl1 = wl[1], wl2 = wl[2];
    float wm0 = wm[0], wm1 = wm[1], wm2 = wm[2];

    float x0 = p[0];
    float x1 = p[D];
    float vl = -CUDART_INF_F;
    float vm = -CUDART_INF_F;

#pragma unroll
    for (int s = 0; s < 28; ++s) {
        float x2 = p[(s + 2) * D];
        float c = fmaf(x0, wl0, fmaf(x1, wl1, x2 * wl2));
        vl = fmaxf(vl, c);
        if (s >= 23) {
            float cm = fmaf(x0, wm0, fmaf(x1, wm1, x2 * wm2));
            vm = fmaxf(vm, cm);
        }
        x0 = x1;
        x1 = x2;
    }
    float vs = x1;  // x[29]

    float* f = feat + (size_t)b * K;
    f[d]         = vl;
    f[D + d]     = vm;
    f[2 * D + d] = vs;
}

// ---------------------------------------------------------------------------
// Packed f32x2 helpers: fma.rn.f32x2 = 2 fp32 FMAs per fma-pipe slot.
// ---------------------------------------------------------------------------
__device__ __forceinline__ unsigned long long pack2(float x, float y) {
    unsigned long long r;
    asm("mov.b64 %0, {%1, %2};" : "=l"(r) : "f"(x), "f"(y));
    return r;
}
__device__ __forceinline__ void unpack2(unsigned long long v, float& x, float& y) {
    asm("mov.b64 {%0, %1}, %2;" : "=f"(x), "=f"(y) : "l"(v));
}
__device__ __forceinline__ void ffma2(unsigned long long& c,
                                      unsigned long long a,
                                      unsigned long long b) {
    asm("fma.rn.f32x2 %0, %1, %2, %0;" : "+l"(c) : "l"(a), "l"(b));
}

// ---------------------------------------------------------------------------
// Kernel 2: fused GEMM + tanh + W2 reduction.
// BM=128 x BN=128 tile, BK=16, 256 threads, 8x8 per-thread microtile.
// Arithmetic intensity: 64 FMA per 64B LDS per thread-kk -> fma and smem
// crossbar co-saturate (was crossbar-bound 2:1 with 4x4).
// ---------------------------------------------------------------------------
#define BM 128
#define BN 128
#define BK 16
#define PAD 4   // keeps LDS.128 alignment (row stride 132 floats = 528B, 16B-aligned)

__global__ __launch_bounds__(256) void gemm_tanh_kernel(
    const float* __restrict__ feat,
    const float* __restrict__ W1,
    const float* __restrict__ W2,
    float* __restrict__ out)
{
    __shared__ float As[BK][BM + PAD];   // As[kk][m]
    __shared__ float Bs[BK][BN + PAD];   // Bs[kk][n]

    const int tx = threadIdx.x;          // 0..255
    const int m0 = blockIdx.x * BM;
    const int n0 = blockIdx.y * BN;

    const int i = tx >> 4;   // 0..15 -> rows i*8 .. i*8+7
    const int j = tx & 15;   // 0..15 -> cols j*8 .. j*8+7

    // Global load mapping: 2 float4 per matrix per thread per k-tile
    const int lr = tx >> 2;          // 0..63 : tile row (rows lr and lr+64)
    const int lk = (tx & 3) << 2;    // 0,4,8,12

    const float* aG = feat + (size_t)(m0 + lr) * K + lk;
    const float* bG = W1   + (size_t)(n0 + lr) * K + lk;

    unsigned long long acc[4][8];    // [m-pair p -> rows 2p,2p+1][n]
#pragma unroll
    for (int p = 0; p < 4; ++p)
#pragma unroll
        for (int n = 0; n < 8; ++n) acc[p][n] = 0ULL;

    // Prefetch first k-tile
    float4 a0 = *(const float4*)(aG);
    float4 a1 = *(const float4*)(aG + (size_t)64 * K);
    float4 b0 = *(const float4*)(bG);
    float4 b1 = *(const float4*)(bG + (size_t)64 * K);

    for (int k0 = 0; k0 < K; k0 += BK) {
        __syncthreads();   // previous tile's compute finished

        // Transposed stores (scalar; 2-way bank conflict acceptable)
#pragma unroll
        for (int q = 0; q < 4; ++q) {
            As[lk + q][lr]      = ((const float*)&a0)[q];
            As[lk + q][lr + 64] = ((const float*)&a1)[q];
            Bs[lk + q][lr]      = ((const float*)&b0)[q];
            Bs[lk + q][lr + 64] = ((const float*)&b1)[q];
        }

        __syncthreads();

        // Prefetch next tile (overlaps with compute below)
        if (k0 + BK < K) {
            a0 = *(const float4*)(aG + k0 + BK);
            a1 = *(const float4*)(aG + (size_t)64 * K + k0 + BK);
            b0 = *(const float4*)(bG + k0 + BK);
            b1 = *(const float4*)(bG + (size_t)64 * K + k0 + BK);
        }

#pragma unroll
        for (int kk = 0; kk < BK; ++kk) {
            float4 aA = *(const float4*)&As[kk][i << 3];
            float4 aB = *(const float4*)&As[kk][(i << 3) + 4];
            float4 bA = *(const float4*)&Bs[kk][j << 3];
            float4 bB = *(const float4*)&Bs[kk][(j << 3) + 4];

            unsigned long long ap[4];
            ap[0] = pack2(aA.x, aA.y);
            ap[1] = pack2(aA.z, aA.w);
            ap[2] = pack2(aB.x, aB.y);
            ap[3] = pack2(aB.z, aB.w);

            float bf[8] = {bA.x, bA.y, bA.z, bA.w, bB.x, bB.y, bB.z, bB.w};
#pragma unroll
            for (int n = 0; n < 8; ++n) {
                unsigned long long bd = pack2(bf[n], bf[n]);
#pragma unroll
                for (int p = 0; p < 4; ++p)
                    ffma2(acc[p][n], ap[p], bd);
            }
        }
    }

    // Epilogue: tanh + W2 weighting, reduce across the 16 j-threads per row.
    float w2v[8];
#pragma unroll
    for (int n = 0; n < 8; ++n) w2v[n] = W2[n0 + (j << 3) + n];

    float part[8];
#pragma unroll
    for (int t = 0; t < 8; ++t) part[t] = 0.f;

#pragma unroll
    for (int p = 0; p < 4; ++p) {
#pragma unroll
        for (int n = 0; n < 8; ++n) {
            float x, y;
            unpack2(acc[p][n], x, y);
            part[2 * p + 0] += tanhf(x) * w2v[n];
            part[2 * p + 1] += tanhf(y) * w2v[n];
        }
    }

    // Butterfly over j (offsets 1..8 stay within the 16-lane half sharing i)
#pragma unroll
    for (int off = 8; off > 0; off >>= 1) {
#pragma unroll
        for (int t = 0; t < 8; ++t)
            part[t] += __shfl_xor_sync(0xFFFFFFFFu, part[t], off);
    }

    if (j == 0) {
#pragma unroll
        for (int t = 0; t < 8; ++t)
            atomicAdd(&out[m0 + (i << 3) + t], part[t]);
    }
}

// ---------------------------------------------------------------------------
// Launch
// ---------------------------------------------------------------------------
extern "C" void kernel_launch(void* const* d_in, const int* in_sizes, int n_in,
                              void* d_out, int out_size)
{
    const float* emb    = (const float*)d_in[0];  // [8192, 30, 512]
    const float* w_long = (const float*)d_in[1];  // [3]
    const float* w_mid  = (const float*)d_in[2];  // [3]
    const float* W1     = (const float*)d_in[3];  // [1024, 1536]
    const float* W2     = (const float*)d_in[4];  // [1, 1024]
    float* out = (float*)d_out;                   // [8192]

    float* feat = nullptr;
    cudaGetSymbolAddress((void**)&feat, g_feat);

    cudaMemsetAsync(out, 0, (size_t)Bsz * sizeof(float));

    {
        int threads = 256;
        int blocks = (Bsz * D) / threads;   // 16384
        feature_kernel<<<blocks, threads>>>(emb, w_long, w_mid, feat);
    }

    {
        dim3 grid(Bsz / BM, H / BN);        // (64, 8) = 512 CTAs
        gemm_tanh_kernel<<<grid, 256>>>(feat, W1, W2, out);
    }
}

// round 5
// speedup vs baseline: 3.1864x; 2.6287x over previous
#include <cuda_runtime.h>
#include <cuda_bf16.h>
#include <math_constants.h>
#include <cstdint>

// Problem constants
static constexpr int Bsz = 8192;
static constexpr int S   = 30;
static constexpr int D   = 512;
static constexpr int H   = 1024;
static constexpr int K   = 1536;   // 3*D

// Scratch: bf16 hi/lo splits of feature matrix and W1 (no device allocs allowed)
__device__ __align__(128) __nv_bfloat16 g_fhi[(size_t)Bsz * K];
__device__ __align__(128) __nv_bfloat16 g_flo[(size_t)Bsz * K];
__device__ __align__(128) __nv_bfloat16 g_whi[(size_t)H * K];
__device__ __align__(128) __nv_bfloat16 g_wlo[(size_t)H * K];

// ---------------------------------------------------------------------------
// Helpers
// ---------------------------------------------------------------------------
__device__ __forceinline__ void split_bf16(float x, __nv_bfloat16& hi, __nv_bfloat16& lo) {
    hi = __float2bfloat16(x);
    lo = __float2bfloat16(x - __bfloat162float(hi));
}

__device__ __forceinline__ uint32_t smem_u32(const void* p) {
    uint32_t a;
    asm("{ .reg .u64 t; cvta.to.shared.u64 t, %1; cvt.u32.u64 %0, t; }" : "=r"(a) : "l"(p));
    return a;
}

__device__ __forceinline__ void cpa16(uint32_t s, const void* g) {
    asm volatile("cp.async.cg.shared.global [%0], [%1], 16;" :: "r"(s), "l"(g) : "memory");
}

__device__ __forceinline__ void ldsm4(uint32_t* r, uint32_t addr) {
    asm volatile("ldmatrix.sync.aligned.m8n8.x4.shared.b16 {%0,%1,%2,%3}, [%4];"
                 : "=r"(r[0]), "=r"(r[1]), "=r"(r[2]), "=r"(r[3]) : "r"(addr));
}

__device__ __forceinline__ void mma16816(float* d, const uint32_t* a, const uint32_t* b) {
    asm volatile(
        "mma.sync.aligned.m16n8k16.row.col.f32.bf16.bf16.f32 "
        "{%0,%1,%2,%3}, {%4,%5,%6,%7}, {%8,%9}, {%0,%1,%2,%3};"
        : "+f"(d[0]), "+f"(d[1]), "+f"(d[2]), "+f"(d[3])
        : "r"(a[0]), "r"(a[1]), "r"(a[2]), "r"(a[3]), "r"(b[0]), "r"(b[1]));
}

__device__ __forceinline__ uint32_t sw128(uint32_t off) {
    return off ^ ((off >> 3) & 0x70);
}

// ---------------------------------------------------------------------------
// Kernel 1: feature extraction -> bf16 (hi, lo) splits
// ---------------------------------------------------------------------------
__global__ __launch_bounds__(256) void feature_kernel(
    const float* __restrict__ emb,
    const float* __restrict__ wl,
    const float* __restrict__ wm,
    __nv_bfloat16* __restrict__ fhi,
    __nv_bfloat16* __restrict__ flo)
{
    int t = blockIdx.x * blockDim.x + threadIdx.x;
    int b = t >> 9;
    int d = t & (D - 1);

    const float* p = emb + (size_t)b * (S * D) + d;

    float wl0 = wl[0], wl1 = wl[1], wl2 = wl[2];
    float wm0 = wm[0], wm1 = wm[1], wm2 = wm[2];

    float x0 = p[0];
    float x1 = p[D];
    float vl = -CUDART_INF_F;
    float vm = -CUDART_INF_F;

#pragma unroll
    for (int s = 0; s < 28; ++s) {
        float x2 = p[(s + 2) * D];
        float c = fmaf(x0, wl0, fmaf(x1, wl1, x2 * wl2));
        vl = fmaxf(vl, c);
        if (s >= 23) {
            float cm = fmaf(x0, wm0, fmaf(x1, wm1, x2 * wm2));
            vm = fmaxf(vm, cm);
        }
        x0 = x1;
        x1 = x2;
    }
    float vs = x1;

    size_t base = (size_t)b * K;
    __nv_bfloat16 hi, lo;
    split_bf16(vl, hi, lo); fhi[base + d] = hi;           flo[base + d] = lo;
    split_bf16(vm, hi, lo); fhi[base + D + d] = hi;       flo[base + D + d] = lo;
    split_bf16(vs, hi, lo); fhi[base + 2 * D + d] = hi;   flo[base + 2 * D + d] = lo;
}

// ---------------------------------------------------------------------------
// Kernel 2: split W1 -> bf16 hi/lo
// ---------------------------------------------------------------------------
__global__ __launch_bounds__(256) void w1_split_kernel(
    const float* __restrict__ W1,
    __nv_bfloat16* __restrict__ whi,
    __nv_bfloat16* __restrict__ wlo)
{
    int i = blockIdx.x * 256 + threadIdx.x;
    float x = W1[i];
    __nv_bfloat16 hi, lo;
    split_bf16(x, hi, lo);
    whi[i] = hi;
    wlo[i] = lo;
}

// ---------------------------------------------------------------------------
// Kernel 3: mma.sync bf16-split GEMM + tanh + W2 reduction.
//   CTA 128x64, BK=64, 8 warps (4m x 2n), warp tile 32x32.
//   hidden = ahi*bhi + ahi*blo + alo*bhi  (fp32 accumulate; drops alo*blo)
// ---------------------------------------------------------------------------
#define GT 256
// per-stage smem region offsets (stage stride 48 KB)
#define OFF_AH 0
#define OFF_AL 16384
#define OFF_BH 32768
#define OFF_BL 40960
#define STAGE 49152
#define GEMM_SMEM (2 * STAGE)   // 96 KB

__device__ __forceinline__ void load_stage(
    uint32_t sbase,
    const __nv_bfloat16* aH, const __nv_bfloat16* aL,
    const __nv_bfloat16* bH, const __nv_bfloat16* bL,
    int k0, int tid)
{
    // A: 128 rows x 128B  -> 1024 x 16B per operand (r = o>>3, c = o&7)
#pragma unroll
    for (int o = tid; o < 1024; o += GT) {
        int r = o >> 3, c = o & 7;
        uint32_t sw = sw128((uint32_t)(r * 128 + c * 16));
        size_t g = (size_t)r * K + k0 + c * 8;
        cpa16(sbase + OFF_AH + sw, aH + g);
        cpa16(sbase + OFF_AL + sw, aL + g);
    }
    // B: 64 rows x 128B -> 512 x 16B per operand
#pragma unroll
    for (int o = tid; o < 512; o += GT) {
        int r = o >> 3, c = o & 7;
        uint32_t sw = sw128((uint32_t)(r * 128 + c * 16));
        size_t g = (size_t)r * K + k0 + c * 8;
        cpa16(sbase + OFF_BH + sw, bH + g);
        cpa16(sbase + OFF_BL + sw, bL + g);
    }
}

__global__ void __launch_bounds__(GT, 2) gemm_mma_kernel(
    const __nv_bfloat16* __restrict__ fhi, const __nv_bfloat16* __restrict__ flo,
    const __nv_bfloat16* __restrict__ whi, const __nv_bfloat16* __restrict__ wlo,
    const float* __restrict__ W2, float* __restrict__ out)
{
    extern __shared__ char smem[];
    const uint32_t sb = smem_u32(smem);
    const int tid  = threadIdx.x;
    const int wid  = tid >> 5;
    const int lane = tid & 31;
    const int wm   = wid & 3;    // 0..3 -> m rows wm*32
    const int wn   = wid >> 2;   // 0..1 -> n cols wn*32
    const int m0   = blockIdx.x * 128;
    const int n0   = blockIdx.y * 64;

    const __nv_bfloat16* aH = fhi + (size_t)m0 * K;
    const __nv_bfloat16* aL = flo + (size_t)m0 * K;
    const __nv_bfloat16* bH = whi + (size_t)n0 * K;
    const __nv_bfloat16* bL = wlo + (size_t)n0 * K;

    float acc[2][4][4];
#pragma unroll
    for (int mt = 0; mt < 2; ++mt)
#pragma unroll
        for (int nt = 0; nt < 4; ++nt)
#pragma unroll
            for (int e = 0; e < 4; ++e) acc[mt][nt][e] = 0.f;

    // Lane-derived ldmatrix row/col components
    const int aRow  = (lane & 15);                       // A: rows 0-15
    const int aKch  = (lane >> 4);                       // A: k 8-chunk 0/1
    const int bRow  = ((lane >> 4) << 3) + (lane & 7);   // B: n-row within 16-group
    const int bKch  = (lane >> 3) & 1;                   // B: k 8-chunk

    // Prologue: 2 stages in flight
    load_stage(sb, aH, aL, bH, bL, 0, tid);
    asm volatile("cp.async.commit_group;" ::: "memory");
    load_stage(sb + STAGE, aH, aL, bH, bL, 64, tid);
    asm volatile("cp.async.commit_group;" ::: "memory");

    for (int c = 0; c < 24; ++c) {
        if (c < 23) asm volatile("cp.async.wait_group 1;" ::: "memory");
        else        asm volatile("cp.async.wait_group 0;" ::: "memory");
        __syncthreads();

        const uint32_t sbase = sb + (c & 1) * STAGE;

#pragma unroll
        for (int ks = 0; ks < 4; ++ks) {
            uint32_t ah[2][4], al[2][4], bh[2][4], bl[2][4];
#pragma unroll
            for (int mt = 0; mt < 2; ++mt) {
                uint32_t off = (uint32_t)((wm * 32 + mt * 16 + aRow) * 128
                                          + ks * 32 + aKch * 16);
                uint32_t sw = sw128(off);
                ldsm4(ah[mt], sbase + OFF_AH + sw);
                ldsm4(al[mt], sbase + OFF_AL + sw);
            }
#pragma unroll
            for (int g = 0; g < 2; ++g) {
                uint32_t off = (uint32_t)((wn * 32 + g * 16 + bRow) * 128
                                          + ks * 32 + bKch * 16);
                uint32_t sw = sw128(off);
                ldsm4(bh[g], sbase + OFF_BH + sw);
                ldsm4(bl[g], sbase + OFF_BL + sw);
            }
#pragma unroll
            for (int mt = 0; mt < 2; ++mt) {
#pragma unroll
                for (int nt = 0; nt < 4; ++nt) {
                    const uint32_t* bhp = &bh[nt >> 1][(nt & 1) * 2];
                    const uint32_t* blp = &bl[nt >> 1][(nt & 1) * 2];
                    mma16816(acc[mt][nt], ah[mt], bhp);
                    mma16816(acc[mt][nt], ah[mt], blp);
                    mma16816(acc[mt][nt], al[mt], bhp);
                }
            }
        }

        __syncthreads();   // everyone done reading this stage
        if (c + 2 < 24) {
            load_stage(sbase, aH, aL, bH, bL, (c + 2) * 64, tid);
            asm volatile("cp.async.commit_group;" ::: "memory");
        }
    }

    // Epilogue: tanh + W2 dot, reduce within quads, atomicAdd per row.
    float w2v[4][2];
#pragma unroll
    for (int nt = 0; nt < 4; ++nt) {
        int col = n0 + wn * 32 + nt * 8 + 2 * (lane & 3);
        w2v[nt][0] = W2[col];
        w2v[nt][1] = W2[col + 1];
    }

#pragma unroll
    for (int mt = 0; mt < 2; ++mt) {
        float p0 = 0.f, p1 = 0.f;
#pragma unroll
        for (int nt = 0; nt < 4; ++nt) {
            p0 += tanhf(acc[mt][nt][0]) * w2v[nt][0]
                + tanhf(acc[mt][nt][1]) * w2v[nt][1];
            p1 += tanhf(acc[mt][nt][2]) * w2v[nt][0]
                + tanhf(acc[mt][nt][3]) * w2v[nt][1];
        }
        p0 += __shfl_xor_sync(0xFFFFFFFFu, p0, 1);
        p0 += __shfl_xor_sync(0xFFFFFFFFu, p0, 2);
        p1 += __shfl_xor_sync(0xFFFFFFFFu, p1, 1);
        p1 += __shfl_xor_sync(0xFFFFFFFFu, p1, 2);
        if ((lane & 3) == 0) {
            int r = m0 + wm * 32 + mt * 16 + (lane >> 2);
            atomicAdd(&out[r], p0);
            atomicAdd(&out[r + 8], p1);
        }
    }
}

// ---------------------------------------------------------------------------
// Launch
// ---------------------------------------------------------------------------
extern "C" void kernel_launch(void* const* d_in, const int* in_sizes, int n_in,
                              void* d_out, int out_size)
{
    const float* emb    = (const float*)d_in[0];  // [8192, 30, 512]
    const float* w_long = (const float*)d_in[1];  // [3]
    const float* w_mid  = (const float*)d_in[2];  // [3]
    const float* W1     = (const float*)d_in[3];  // [1024, 1536]
    const float* W2     = (const float*)d_in[4];  // [1, 1024]
    float* out = (float*)d_out;                   // [8192]

    __nv_bfloat16 *fhi, *flo, *whi, *wlo;
    cudaGetSymbolAddress((void**)&fhi, g_fhi);
    cudaGetSymbolAddress((void**)&flo, g_flo);
    cudaGetSymbolAddress((void**)&whi, g_whi);
    cudaGetSymbolAddress((void**)&wlo, g_wlo);

    cudaFuncSetAttribute(gemm_mma_kernel,
                         cudaFuncAttributeMaxDynamicSharedMemorySize, GEMM_SMEM);

    cudaMemsetAsync(out, 0, (size_t)Bsz * sizeof(float));

    feature_kernel<<<(Bsz * D) / 256, 256>>>(emb, w_long, w_mid, fhi, flo);
    w1_split_kernel<<<(H * K) / 256, 256>>>(W1, whi, wlo);

    dim3 grid(Bsz / 128, H / 64);   // (64, 16) = 1024 CTAs
    gemm_mma_kernel<<<grid, GT, GEMM_SMEM>>>(fhi, flo, whi, wlo, W2, out);
}

// round 6
// speedup vs baseline: 3.8429x; 1.2060x over previous
#include <cuda_runtime.h>
#include <cuda_fp16.h>
#include <math_constants.h>
#include <cstdint>

// Problem constants
static constexpr int Bsz = 8192;
static constexpr int S   = 30;
static constexpr int D   = 512;
static constexpr int H   = 1024;
static constexpr int K   = 1536;   // 3*D

// Scratch: fp16 hi/lo split of features, fp16 W1 (no device allocs allowed)
__device__ __align__(128) __half g_fhi[(size_t)Bsz * K];
__device__ __align__(128) __half g_flo[(size_t)Bsz * K];
__device__ __align__(128) __half g_whi[(size_t)H * K];

// ---------------------------------------------------------------------------
// Helpers
// ---------------------------------------------------------------------------
__device__ __forceinline__ void split_fp16(float x, __half& hi, __half& lo) {
    hi = __float2half_rn(x);
    lo = __float2half_rn(x - __half2float(hi));
}

__device__ __forceinline__ uint32_t smem_u32(const void* p) {
    uint32_t a;
    asm("{ .reg .u64 t; cvta.to.shared.u64 t, %1; cvt.u32.u64 %0, t; }" : "=r"(a) : "l"(p));
    return a;
}

__device__ __forceinline__ void cpa16(uint32_t s, const void* g) {
    asm volatile("cp.async.cg.shared.global [%0], [%1], 16;" :: "r"(s), "l"(g) : "memory");
}

__device__ __forceinline__ void ldsm4(uint32_t* r, uint32_t addr) {
    asm volatile("ldmatrix.sync.aligned.m8n8.x4.shared.b16 {%0,%1,%2,%3}, [%4];"
                 : "=r"(r[0]), "=r"(r[1]), "=r"(r[2]), "=r"(r[3]) : "r"(addr));
}

__device__ __forceinline__ void mma16816(float* d, const uint32_t* a, const uint32_t* b) {
    asm volatile(
        "mma.sync.aligned.m16n8k16.row.col.f32.f16.f16.f32 "
        "{%0,%1,%2,%3}, {%4,%5,%6,%7}, {%8,%9}, {%0,%1,%2,%3};"
        : "+f"(d[0]), "+f"(d[1]), "+f"(d[2]), "+f"(d[3])
        : "r"(a[0]), "r"(a[1]), "r"(a[2]), "r"(a[3]), "r"(b[0]), "r"(b[1]));
}

__device__ __forceinline__ uint32_t sw128(uint32_t off) {
    return off ^ ((off >> 3) & 0x70);
}

// ---------------------------------------------------------------------------
// Kernel 1: feature extraction -> fp16 (hi, lo) split
// ---------------------------------------------------------------------------
__global__ __launch_bounds__(256) void feature_kernel(
    const float* __restrict__ emb,
    const float* __restrict__ wl,
    const float* __restrict__ wm,
    __half* __restrict__ fhi,
    __half* __restrict__ flo)
{
    int t = blockIdx.x * blockDim.x + threadIdx.x;
    int b = t >> 9;
    int d = t & (D - 1);

    const float* p = emb + (size_t)b * (S * D) + d;

    float wl0 = wl[0], wl1 = wl[1], wl2 = wl[2];
    float wm0 = wm[0], wm1 = wm[1], wm2 = wm[2];

    float x0 = p[0];
    float x1 = p[D];
    float vl = -CUDART_INF_F;
    float vm = -CUDART_INF_F;

#pragma unroll
    for (int s = 0; s < 28; ++s) {
        float x2 = p[(s + 2) * D];
        float c = fmaf(x0, wl0, fmaf(x1, wl1, x2 * wl2));
        vl = fmaxf(vl, c);
        if (s >= 23) {
            float cm = fmaf(x0, wm0, fmaf(x1, wm1, x2 * wm2));
            vm = fmaxf(vm, cm);
        }
        x0 = x1;
        x1 = x2;
    }
    float vs = x1;

    size_t base = (size_t)b * K;
    __half hi, lo;
    split_fp16(vl, hi, lo); fhi[base + d] = hi;           flo[base + d] = lo;
    split_fp16(vm, hi, lo); fhi[base + D + d] = hi;       flo[base + D + d] = lo;
    split_fp16(vs, hi, lo); fhi[base + 2 * D + d] = hi;   flo[base + 2 * D + d] = lo;
}

// ---------------------------------------------------------------------------
// Kernel 2: W1 -> fp16
// ---------------------------------------------------------------------------
__global__ __launch_bounds__(256) void w1_cvt_kernel(
    const float* __restrict__ W1,
    __half* __restrict__ whi)
{
    int i = blockIdx.x * 256 + threadIdx.x;
    whi[i] = __float2half_rn(W1[i]);
}

// ---------------------------------------------------------------------------
// Kernel 3: mma.sync fp16-split GEMM + tanh + W2 reduction.
//   CTA 128x64, BK=64, 8 warps (4m x 2n), warp tile 32x32.
//   hidden = ahi*bhi + alo*bhi = a * fp16(W1)   (fp32 accumulate)
// ---------------------------------------------------------------------------
#define GT 256
// per-stage smem region offsets (stage stride 40 KB)
#define OFF_AH 0
#define OFF_AL 16384
#define OFF_BH 32768
#define STAGE 40960
#define GEMM_SMEM (2 * STAGE)   // 80 KB -> 2 CTAs/SM

__device__ __forceinline__ void load_stage(
    uint32_t sbase,
    const __half* aH, const __half* aL, const __half* bH,
    int k0, int tid)
{
    // A: 128 rows x 128B -> 1024 x 16B per operand (r = o>>3, c = o&7)
#pragma unroll
    for (int o = tid; o < 1024; o += GT) {
        int r = o >> 3, c = o & 7;
        uint32_t sw = sw128((uint32_t)(r * 128 + c * 16));
        size_t g = (size_t)r * K + k0 + c * 8;
        cpa16(sbase + OFF_AH + sw, aH + g);
        cpa16(sbase + OFF_AL + sw, aL + g);
    }
    // B: 64 rows x 128B -> 512 x 16B
#pragma unroll
    for (int o = tid; o < 512; o += GT) {
        int r = o >> 3, c = o & 7;
        uint32_t sw = sw128((uint32_t)(r * 128 + c * 16));
        size_t g = (size_t)r * K + k0 + c * 8;
        cpa16(sbase + OFF_BH + sw, bH + g);
    }
}

__global__ void __launch_bounds__(GT, 2) gemm_mma_kernel(
    const __half* __restrict__ fhi, const __half* __restrict__ flo,
    const __half* __restrict__ whi,
    const float* __restrict__ W2, float* __restrict__ out)
{
    extern __shared__ char smem[];
    const uint32_t sb = smem_u32(smem);
    const int tid  = threadIdx.x;
    const int wid  = tid >> 5;
    const int lane = tid & 31;
    const int wm   = wid & 3;    // 0..3 -> m rows wm*32
    const int wn   = wid >> 2;   // 0..1 -> n cols wn*32
    const int m0   = blockIdx.x * 128;
    const int n0   = blockIdx.y * 64;

    const __half* aH = fhi + (size_t)m0 * K;
    const __half* aL = flo + (size_t)m0 * K;
    const __half* bH = whi + (size_t)n0 * K;

    float acc[2][4][4];
#pragma unroll
    for (int mt = 0; mt < 2; ++mt)
#pragma unroll
        for (int nt = 0; nt < 4; ++nt)
#pragma unroll
            for (int e = 0; e < 4; ++e) acc[mt][nt][e] = 0.f;

    // Lane-derived ldmatrix addressing
    const int aRow  = (lane & 15);                       // A: rows 0-15
    const int aKch  = (lane >> 4);                       // A: k 8-chunk 0/1
    const int bRow  = ((lane >> 4) << 3) + (lane & 7);   // B: n-row in 16-group
    const int bKch  = (lane >> 3) & 1;                   // B: k 8-chunk

    // Prologue: 2 stages in flight
    load_stage(sb, aH, aL, bH, 0, tid);
    asm volatile("cp.async.commit_group;" ::: "memory");
    load_stage(sb + STAGE, aH, aL, bH, 64, tid);
    asm volatile("cp.async.commit_group;" ::: "memory");

    for (int c = 0; c < 24; ++c) {
        if (c < 23) asm volatile("cp.async.wait_group 1;" ::: "memory");
        else        asm volatile("cp.async.wait_group 0;" ::: "memory");
        __syncthreads();

        const uint32_t sbase = sb + (c & 1) * STAGE;

#pragma unroll
        for (int ks = 0; ks < 4; ++ks) {
            uint32_t ah[2][4], al[2][4], bh[2][4];
#pragma unroll
            for (int mt = 0; mt < 2; ++mt) {
                uint32_t off = (uint32_t)((wm * 32 + mt * 16 + aRow) * 128
                                          + ks * 32 + aKch * 16);
                uint32_t sw = sw128(off);
                ldsm4(ah[mt], sbase + OFF_AH + sw);
                ldsm4(al[mt], sbase + OFF_AL + sw);
            }
#pragma unroll
            for (int g = 0; g < 2; ++g) {
                uint32_t off = (uint32_t)((wn * 32 + g * 16 + bRow) * 128
                                          + ks * 32 + bKch * 16);
                uint32_t sw = sw128(off);
                ldsm4(bh[g], sbase + OFF_BH + sw);
            }
#pragma unroll
            for (int mt = 0; mt < 2; ++mt) {
#pragma unroll
                for (int nt = 0; nt < 4; ++nt) {
                    const uint32_t* bhp = &bh[nt >> 1][(nt & 1) * 2];
                    mma16816(acc[mt][nt], ah[mt], bhp);
                    mma16816(acc[mt][nt], al[mt], bhp);
                }
            }
        }

        __syncthreads();   // everyone done reading this stage
        if (c + 2 < 24) {
            load_stage(sbase, aH, aL, bH, (c + 2) * 64, tid);
            asm volatile("cp.async.commit_group;" ::: "memory");
        }
    }

    // Epilogue: tanh + W2 dot, reduce within quads, atomicAdd per row.
    float w2v[4][2];
#pragma unroll
    for (int nt = 0; nt < 4; ++nt) {
        int col = n0 + wn * 32 + nt * 8 + 2 * (lane & 3);
        w2v[nt][0] = W2[col];
        w2v[nt][1] = W2[col + 1];
    }

#pragma unroll
    for (int mt = 0; mt < 2; ++mt) {
        float p0 = 0.f, p1 = 0.f;
#pragma unroll
        for (int nt = 0; nt < 4; ++nt) {
            p0 += tanhf(acc[mt][nt][0]) * w2v[nt][0]
                + tanhf(acc[mt][nt][1]) * w2v[nt][1];
            p1 += tanhf(acc[mt][nt][2]) * w2v[nt][0]
                + tanhf(acc[mt][nt][3]) * w2v[nt][1];
        }
        p0 += __shfl_xor_sync(0xFFFFFFFFu, p0, 1);
        p0 += __shfl_xor_sync(0xFFFFFFFFu, p0, 2);
        p1 += __shfl_xor_sync(0xFFFFFFFFu, p1, 1);
        p1 += __shfl_xor_sync(0xFFFFFFFFu, p1, 2);
        if ((lane & 3) == 0) {
            int r = m0 + wm * 32 + mt * 16 + (lane >> 2);
            atomicAdd(&out[r], p0);
            atomicAdd(&out[r + 8], p1);
        }
    }
}

// ---------------------------------------------------------------------------
// Launch
// ---------------------------------------------------------------------------
extern "C" void kernel_launch(void* const* d_in, const int* in_sizes, int n_in,
                              void* d_out, int out_size)
{
    const float* emb    = (const float*)d_in[0];  // [8192, 30, 512]
    const float* w_long = (const float*)d_in[1];  // [3]
    const float* w_mid  = (const float*)d_in[2];  // [3]
    const float* W1     = (const float*)d_in[3];  // [1024, 1536]
    const float* W2     = (const float*)d_in[4];  // [1, 1024]
    float* out = (float*)d_out;                   // [8192]

    __half *fhi, *flo, *whi;
    cudaGetSymbolAddress((void**)&fhi, g_fhi);
    cudaGetSymbolAddress((void**)&flo, g_flo);
    cudaGetSymbolAddress((void**)&whi, g_whi);

    cudaFuncSetAttribute(gemm_mma_kernel,
                         cudaFuncAttributeMaxDynamicSharedMemorySize, GEMM_SMEM);

    cudaMemsetAsync(out, 0, (size_t)Bsz * sizeof(float));

    feature_kernel<<<(Bsz * D) / 256, 256>>>(emb, w_long, w_mid, fhi, flo);
    w1_cvt_kernel<<<(H * K) / 256, 256>>>(W1, whi);

    dim3 grid(Bsz / 128, H / 64);   // (64, 16) = 1024 CTAs
    gemm_mma_kernel<<<grid, GT, GEMM_SMEM>>>(fhi, flo, whi, W2, out);
}

// round 7
// speedup vs baseline: 5.2611x; 1.3690x over previous
#include <cuda_runtime.h>
#include <cuda_fp16.h>
#include <math_constants.h>
#include <cstdint>

// Problem constants
static constexpr int Bsz = 8192;
static constexpr int S   = 30;
static constexpr int D   = 512;
static constexpr int H   = 1024;
static constexpr int K   = 1536;   // 3*D

// Scratch: fp16 features and fp16 W1 (no device allocs allowed)
__device__ __align__(128) __half g_fh[(size_t)Bsz * K];
__device__ __align__(128) __half g_wh[(size_t)H * K];

// ---------------------------------------------------------------------------
// Helpers
// ---------------------------------------------------------------------------
__device__ __forceinline__ uint32_t smem_u32(const void* p) {
    uint32_t a;
    asm("{ .reg .u64 t; cvta.to.shared.u64 t, %1; cvt.u32.u64 %0, t; }" : "=r"(a) : "l"(p));
    return a;
}

__device__ __forceinline__ void cpa16(uint32_t s, const void* g) {
    asm volatile("cp.async.cg.shared.global [%0], [%1], 16;" :: "r"(s), "l"(g) : "memory");
}

__device__ __forceinline__ void ldsm4(uint32_t* r, uint32_t addr) {
    asm volatile("ldmatrix.sync.aligned.m8n8.x4.shared.b16 {%0,%1,%2,%3}, [%4];"
                 : "=r"(r[0]), "=r"(r[1]), "=r"(r[2]), "=r"(r[3]) : "r"(addr));
}

__device__ __forceinline__ void mma16816(float* d, const uint32_t* a, const uint32_t* b) {
    asm volatile(
        "mma.sync.aligned.m16n8k16.row.col.f32.f16.f16.f32 "
        "{%0,%1,%2,%3}, {%4,%5,%6,%7}, {%8,%9}, {%0,%1,%2,%3};"
        : "+f"(d[0]), "+f"(d[1]), "+f"(d[2]), "+f"(d[3])
        : "r"(a[0]), "r"(a[1]), "r"(a[2]), "r"(a[3]), "r"(b[0]), "r"(b[1]));
}

__device__ __forceinline__ uint32_t sw128(uint32_t off) {
    return off ^ ((off >> 3) & 0x70);
}

// ---------------------------------------------------------------------------
// Kernel 1: feature extraction -> fp16
// ---------------------------------------------------------------------------
__global__ __launch_bounds__(256) void feature_kernel(
    const float* __restrict__ emb,
    const float* __restrict__ wl,
    const float* __restrict__ wm,
    __half* __restrict__ fh)
{
    int t = blockIdx.x * blockDim.x + threadIdx.x;
    int b = t >> 9;
    int d = t & (D - 1);

    const float* p = emb + (size_t)b * (S * D) + d;

    float wl0 = wl[0], wl1 = wl[1], wl2 = wl[2];
    float wm0 = wm[0], wm1 = wm[1], wm2 = wm[2];

    float x0 = p[0];
    float x1 = p[D];
    float vl = -CUDART_INF_F;
    float vm = -CUDART_INF_F;

#pragma unroll
    for (int s = 0; s < 28; ++s) {
        float x2 = p[(s + 2) * D];
        float c = fmaf(x0, wl0, fmaf(x1, wl1, x2 * wl2));
        vl = fmaxf(vl, c);
        if (s >= 23) {
            float cm = fmaf(x0, wm0, fmaf(x1, wm1, x2 * wm2));
            vm = fmaxf(vm, cm);
        }
        x0 = x1;
        x1 = x2;
    }
    float vs = x1;

    size_t base = (size_t)b * K;
    fh[base + d]         = __float2half_rn(vl);
    fh[base + D + d]     = __float2half_rn(vm);
    fh[base + 2 * D + d] = __float2half_rn(vs);
}

// ---------------------------------------------------------------------------
// Kernel 2: W1 -> fp16
// ---------------------------------------------------------------------------
__global__ __launch_bounds__(256) void w1_cvt_kernel(
    const float* __restrict__ W1,
    __half* __restrict__ wh)
{
    int i = blockIdx.x * 256 + threadIdx.x;
    wh[i] = __float2half_rn(W1[i]);
}

// ---------------------------------------------------------------------------
// Kernel 3: mma.sync fp16 GEMM + tanh + W2 reduction.
//   CTA 128x128, BK=64, 8 warps (4m x 2n), warp tile 32x64, 3-stage cp.async.
// ---------------------------------------------------------------------------
#define GT 256
#define OFF_A 0
#define OFF_B 16384
#define STAGE 32768
#define NSTAGE 3
#define GEMM_SMEM (NSTAGE * STAGE)   // 96 KB -> 2 CTAs/SM

__device__ __forceinline__ void load_stage(
    uint32_t sbase, const __half* aG, const __half* bG, int k0, int tid)
{
    // A: 128 rows x 8 chunks of 16B; B: same.
#pragma unroll
    for (int o = tid; o < 1024; o += GT) {
        int r = o >> 3, c = o & 7;
        uint32_t sw = sw128((uint32_t)(r * 128 + c * 16));
        size_t g = (size_t)r * K + k0 + c * 8;
        cpa16(sbase + OFF_A + sw, aG + g);
        cpa16(sbase + OFF_B + sw, bG + g);
    }
}

__global__ void __launch_bounds__(GT, 2) gemm_mma_kernel(
    const __half* __restrict__ fh, const __half* __restrict__ wh,
    const float* __restrict__ W2, float* __restrict__ out)
{
    extern __shared__ char smem[];
    const uint32_t sb = smem_u32(smem);
    const int tid  = threadIdx.x;
    const int wid  = tid >> 5;
    const int lane = tid & 31;
    const int wm   = wid & 3;    // m rows wm*32
    const int wn   = wid >> 2;   // n cols wn*64
    const int m0   = blockIdx.x * 128;
    const int n0   = blockIdx.y * 128;

    const __half* aG = fh + (size_t)m0 * K;
    const __half* bG = wh + (size_t)n0 * K;

    float acc[2][8][4];
#pragma unroll
    for (int mt = 0; mt < 2; ++mt)
#pragma unroll
        for (int nt = 0; nt < 8; ++nt)
#pragma unroll
            for (int e = 0; e < 4; ++e) acc[mt][nt][e] = 0.f;

    // Lane-derived ldmatrix addressing (validated in R5/R6)
    const int aRow = (lane & 15);
    const int aKch = (lane >> 4);
    const int bRow = ((lane >> 4) << 3) + (lane & 7);
    const int bKch = (lane >> 3) & 1;

    // Prologue: 3 stages in flight
    load_stage(sb,             aG, bG, 0,   tid);
    asm volatile("cp.async.commit_group;" ::: "memory");
    load_stage(sb + STAGE,     aG, bG, 64,  tid);
    asm volatile("cp.async.commit_group;" ::: "memory");
    load_stage(sb + 2 * STAGE, aG, bG, 128, tid);
    asm volatile("cp.async.commit_group;" ::: "memory");

    uint32_t sbase = sb;
    for (int c = 0; c < 24; ++c) {
        if (c <= 21)      asm volatile("cp.async.wait_group 2;" ::: "memory");
        else if (c == 22) asm volatile("cp.async.wait_group 1;" ::: "memory");
        else              asm volatile("cp.async.wait_group 0;" ::: "memory");
        __syncthreads();

#pragma unroll
        for (int ks = 0; ks < 4; ++ks) {
            uint32_t ah[2][4], bh[4][4];
#pragma unroll
            for (int mt = 0; mt < 2; ++mt) {
                uint32_t off = (uint32_t)((wm * 32 + mt * 16 + aRow) * 128
                                          + ks * 32 + aKch * 16);
                ldsm4(ah[mt], sbase + OFF_A + sw128(off));
            }
#pragma unroll
            for (int g = 0; g < 4; ++g) {
                uint32_t off = (uint32_t)((wn * 64 + g * 16 + bRow) * 128
                                          + ks * 32 + bKch * 16);
                ldsm4(bh[g], sbase + OFF_B + sw128(off));
            }
#pragma unroll
            for (int mt = 0; mt < 2; ++mt) {
#pragma unroll
                for (int nt = 0; nt < 8; ++nt) {
                    const uint32_t* bp = &bh[nt >> 1][(nt & 1) * 2];
                    mma16816(acc[mt][nt], ah[mt], bp);
                }
            }
        }

        __syncthreads();   // all warps done reading this stage
        if (c + 3 < 24) {
            load_stage(sbase, aG, bG, (c + 3) * 64, tid);
            asm volatile("cp.async.commit_group;" ::: "memory");
        }
        sbase += STAGE;
        if (sbase == sb + NSTAGE * STAGE) sbase = sb;
    }

    // Epilogue: tanh + W2 dot, quad reduce, atomicAdd per row.
    float w2v[8][2];
#pragma unroll
    for (int nt = 0; nt < 8; ++nt) {
        int col = n0 + wn * 64 + nt * 8 + 2 * (lane & 3);
        w2v[nt][0] = W2[col];
        w2v[nt][1] = W2[col + 1];
    }

#pragma unroll
    for (int mt = 0; mt < 2; ++mt) {
        float p0 = 0.f, p1 = 0.f;
#pragma unroll
        for (int nt = 0; nt < 8; ++nt) {
            p0 += tanhf(acc[mt][nt][0]) * w2v[nt][0]
                + tanhf(acc[mt][nt][1]) * w2v[nt][1];
            p1 += tanhf(acc[mt][nt][2]) * w2v[nt][0]
                + tanhf(acc[mt][nt][3]) * w2v[nt][1];
        }
        p0 += __shfl_xor_sync(0xFFFFFFFFu, p0, 1);
        p0 += __shfl_xor_sync(0xFFFFFFFFu, p0, 2);
        p1 += __shfl_xor_sync(0xFFFFFFFFu, p1, 1);
        p1 += __shfl_xor_sync(0xFFFFFFFFu, p1, 2);
        if ((lane & 3) == 0) {
            int r = m0 + wm * 32 + mt * 16 + (lane >> 2);
            atomicAdd(&out[r], p0);
            atomicAdd(&out[r + 8], p1);
        }
    }
}

// ---------------------------------------------------------------------------
// Launch
// ---------------------------------------------------------------------------
extern "C" void kernel_launch(void* const* d_in, const int* in_sizes, int n_in,
                              void* d_out, int out_size)
{
    const float* emb    = (const float*)d_in[0];  // [8192, 30, 512]
    const float* w_long = (const float*)d_in[1];  // [3]
    const float* w_mid  = (const float*)d_in[2];  // [3]
    const float* W1     = (const float*)d_in[3];  // [1024, 1536]
    const float* W2     = (const float*)d_in[4];  // [1, 1024]
    float* out = (float*)d_out;                   // [8192]

    __half *fh, *wh;
    cudaGetSymbolAddress((void**)&fh, g_fh);
    cudaGetSymbolAddress((void**)&wh, g_wh);

    cudaFuncSetAttribute(gemm_mma_kernel,
                         cudaFuncAttributeMaxDynamicSharedMemorySize, GEMM_SMEM);

    cudaMemsetAsync(out, 0, (size_t)Bsz * sizeof(float));

    feature_kernel<<<(Bsz * D) / 256, 256>>>(emb, w_long, w_mid, fh);
    w1_cvt_kernel<<<(H * K) / 256, 256>>>(W1, wh);

    dim3 grid(Bsz / 128, H / 128);   // (64, 8) = 512 CTAs
    gemm_mma_kernel<<<grid, GT, GEMM_SMEM>>>(fh, wh, W2, out);
}

// round 8
// speedup vs baseline: 5.3783x; 1.0223x over previous
#include <cuda_runtime.h>
#include <cuda_fp16.h>
#include <math_constants.h>
#include <cstdint>

// Problem constants
static constexpr int Bsz = 8192;
static constexpr int S   = 30;
static constexpr int D   = 512;
static constexpr int H   = 1024;
static constexpr int K   = 1536;   // 3*D

static constexpr int NCHUNK = 4;
static constexpr int BCH    = Bsz / NCHUNK;   // 2048 rows per pipeline chunk

// Scratch: fp16 features and fp16 W1 (no device allocs allowed)
__device__ __align__(128) __half g_fh[(size_t)Bsz * K];
__device__ __align__(128) __half g_wh[(size_t)H * K];

// ---------------------------------------------------------------------------
// Helpers
// ---------------------------------------------------------------------------
__device__ __forceinline__ uint32_t smem_u32(const void* p) {
    uint32_t a;
    asm("{ .reg .u64 t; cvta.to.shared.u64 t, %1; cvt.u32.u64 %0, t; }" : "=r"(a) : "l"(p));
    return a;
}

__device__ __forceinline__ void cpa16(uint32_t s, const void* g) {
    asm volatile("cp.async.cg.shared.global [%0], [%1], 16;" :: "r"(s), "l"(g) : "memory");
}

__device__ __forceinline__ void ldsm4(uint32_t* r, uint32_t addr) {
    asm volatile("ldmatrix.sync.aligned.m8n8.x4.shared.b16 {%0,%1,%2,%3}, [%4];"
                 : "=r"(r[0]), "=r"(r[1]), "=r"(r[2]), "=r"(r[3]) : "r"(addr));
}

__device__ __forceinline__ void mma16816(float* d, const uint32_t* a, const uint32_t* b) {
    asm volatile(
        "mma.sync.aligned.m16n8k16.row.col.f32.f16.f16.f32 "
        "{%0,%1,%2,%3}, {%4,%5,%6,%7}, {%8,%9}, {%0,%1,%2,%3};"
        : "+f"(d[0]), "+f"(d[1]), "+f"(d[2]), "+f"(d[3])
        : "r"(a[0]), "r"(a[1]), "r"(a[2]), "r"(a[3]), "r"(b[0]), "r"(b[1]));
}

__device__ __forceinline__ uint32_t sw128(uint32_t off) {
    return off ^ ((off >> 3) & 0x70);
}

// ---------------------------------------------------------------------------
// Kernel 1: feature extraction -> fp16 (per batch chunk)
// ---------------------------------------------------------------------------
__global__ __launch_bounds__(256) void feature_kernel(
    const float* __restrict__ emb,
    const float* __restrict__ wl,
    const float* __restrict__ wm,
    __half* __restrict__ fh)
{
    int t = blockIdx.x * blockDim.x + threadIdx.x;
    int b = t >> 9;
    int d = t & (D - 1);

    const float* p = emb + (size_t)b * (S * D) + d;

    float wl0 = wl[0], wl1 = wl[1], wl2 = wl[2];
    float wm0 = wm[0], wm1 = wm[1], wm2 = wm[2];

    float x0 = p[0];
    float x1 = p[D];
    float vl = -CUDART_INF_F;
    float vm = -CUDART_INF_F;

#pragma unroll
    for (int s = 0; s < 28; ++s) {
        float x2 = p[(s + 2) * D];
        float c = fmaf(x0, wl0, fmaf(x1, wl1, x2 * wl2));
        vl = fmaxf(vl, c);
        if (s >= 23) {
            float cm = fmaf(x0, wm0, fmaf(x1, wm1, x2 * wm2));
            vm = fmaxf(vm, cm);
        }
        x0 = x1;
        x1 = x2;
    }
    float vs = x1;

    size_t base = (size_t)b * K;
    fh[base + d]         = __float2half_rn(vl);
    fh[base + D + d]     = __float2half_rn(vm);
    fh[base + 2 * D + d] = __float2half_rn(vs);
}

// ---------------------------------------------------------------------------
// Kernel 2: W1 -> fp16
// ---------------------------------------------------------------------------
__global__ __launch_bounds__(256) void w1_cvt_kernel(
    const float* __restrict__ W1,
    __half* __restrict__ wh)
{
    int i = blockIdx.x * 256 + threadIdx.x;
    wh[i] = __float2half_rn(W1[i]);
}

// ---------------------------------------------------------------------------
// Kernel 3: mma.sync fp16 GEMM + tanh + W2 reduction (per batch chunk).
//   CTA 128x128, BK=64, 8 warps (4m x 2n), warp tile 32x64, 3-stage cp.async.
// ---------------------------------------------------------------------------
#define GT 256
#define OFF_A 0
#define OFF_B 16384
#define STAGE 32768
#define NSTAGE 3
#define GEMM_SMEM (NSTAGE * STAGE)   // 96 KB -> 2 CTAs/SM

__device__ __forceinline__ void load_stage(
    uint32_t sbase, const __half* aG, const __half* bG, int k0, int tid)
{
#pragma unroll
    for (int o = tid; o < 1024; o += GT) {
        int r = o >> 3, c = o & 7;
        uint32_t sw = sw128((uint32_t)(r * 128 + c * 16));
        size_t g = (size_t)r * K + k0 + c * 8;
        cpa16(sbase + OFF_A + sw, aG + g);
        cpa16(sbase + OFF_B + sw, bG + g);
    }
}

__global__ void __launch_bounds__(GT, 2) gemm_mma_kernel(
    const __half* __restrict__ fh, const __half* __restrict__ wh,
    const float* __restrict__ W2, float* __restrict__ out)
{
    extern __shared__ char smem[];
    const uint32_t sb = smem_u32(smem);
    const int tid  = threadIdx.x;
    const int wid  = tid >> 5;
    const int lane = tid & 31;
    const int wm   = wid & 3;
    const int wn   = wid >> 2;
    const int m0   = blockIdx.x * 128;
    const int n0   = blockIdx.y * 128;

    const __half* aG = fh + (size_t)m0 * K;
    const __half* bG = wh + (size_t)n0 * K;

    float acc[2][8][4];
#pragma unroll
    for (int mt = 0; mt < 2; ++mt)
#pragma unroll
        for (int nt = 0; nt < 8; ++nt)
#pragma unroll
            for (int e = 0; e < 4; ++e) acc[mt][nt][e] = 0.f;

    const int aRow = (lane & 15);
    const int aKch = (lane >> 4);
    const int bRow = ((lane >> 4) << 3) + (lane & 7);
    const int bKch = (lane >> 3) & 1;

    load_stage(sb,             aG, bG, 0,   tid);
    asm volatile("cp.async.commit_group;" ::: "memory");
    load_stage(sb + STAGE,     aG, bG, 64,  tid);
    asm volatile("cp.async.commit_group;" ::: "memory");
    load_stage(sb + 2 * STAGE, aG, bG, 128, tid);
    asm volatile("cp.async.commit_group;" ::: "memory");

    uint32_t sbase = sb;
    for (int c = 0; c < 24; ++c) {
        if (c <= 21)      asm volatile("cp.async.wait_group 2;" ::: "memory");
        else if (c == 22) asm volatile("cp.async.wait_group 1;" ::: "memory");
        else              asm volatile("cp.async.wait_group 0;" ::: "memory");
        __syncthreads();

#pragma unroll
        for (int ks = 0; ks < 4; ++ks) {
            uint32_t ah[2][4], bh[4][4];
#pragma unroll
            for (int mt = 0; mt < 2; ++mt) {
                uint32_t off = (uint32_t)((wm * 32 + mt * 16 + aRow) * 128
                                          + ks * 32 + aKch * 16);
                ldsm4(ah[mt], sbase + OFF_A + sw128(off));
            }
#pragma unroll
            for (int g = 0; g < 4; ++g) {
                uint32_t off = (uint32_t)((wn * 64 + g * 16 + bRow) * 128
                                          + ks * 32 + bKch * 16);
                ldsm4(bh[g], sbase + OFF_B + sw128(off));
            }
#pragma unroll
            for (int mt = 0; mt < 2; ++mt) {
#pragma unroll
                for (int nt = 0; nt < 8; ++nt) {
                    const uint32_t* bp = &bh[nt >> 1][(nt & 1) * 2];
                    mma16816(acc[mt][nt], ah[mt], bp);
                }
            }
        }

        __syncthreads();
        if (c + 3 < 24) {
            load_stage(sbase, aG, bG, (c + 3) * 64, tid);
            asm volatile("cp.async.commit_group;" ::: "memory");
        }
        sbase += STAGE;
        if (sbase == sb + NSTAGE * STAGE) sbase = sb;
    }

    float w2v[8][2];
#pragma unroll
    for (int nt = 0; nt < 8; ++nt) {
        int col = n0 + wn * 64 + nt * 8 + 2 * (lane & 3);
        w2v[nt][0] = W2[col];
        w2v[nt][1] = W2[col + 1];
    }

#pragma unroll
    for (int mt = 0; mt < 2; ++mt) {
        float p0 = 0.f, p1 = 0.f;
#pragma unroll
        for (int nt = 0; nt < 8; ++nt) {
            p0 += tanhf(acc[mt][nt][0]) * w2v[nt][0]
                + tanhf(acc[mt][nt][1]) * w2v[nt][1];
            p1 += tanhf(acc[mt][nt][2]) * w2v[nt][0]
                + tanhf(acc[mt][nt][3]) * w2v[nt][1];
        }
        p0 += __shfl_xor_sync(0xFFFFFFFFu, p0, 1);
        p0 += __shfl_xor_sync(0xFFFFFFFFu, p0, 2);
        p1 += __shfl_xor_sync(0xFFFFFFFFu, p1, 1);
        p1 += __shfl_xor_sync(0xFFFFFFFFu, p1, 2);
        if ((lane & 3) == 0) {
            int r = m0 + wm * 32 + mt * 16 + (lane >> 2);
            atomicAdd(&out[r], p0);
            atomicAdd(&out[r + 8], p1);
        }
    }
}

// ---------------------------------------------------------------------------
// Launch: fork-join 2-stream pipeline (feature chunks || gemm chunks)
// ---------------------------------------------------------------------------
extern "C" void kernel_launch(void* const* d_in, const int* in_sizes, int n_in,
                              void* d_out, int out_size)
{
    const float* emb    = (const float*)d_in[0];  // [8192, 30, 512]
    const float* w_long = (const float*)d_in[1];  // [3]
    const float* w_mid  = (const float*)d_in[2];  // [3]
    const float* W1     = (const float*)d_in[3];  // [1024, 1536]
    const float* W2     = (const float*)d_in[4];  // [1, 1024]
    float* out = (float*)d_out;                   // [8192]

    __half *fh, *wh;
    cudaGetSymbolAddress((void**)&fh, g_fh);
    cudaGetSymbolAddress((void**)&wh, g_wh);

    // One-time host resources (streams/events are not device memory; the
    // captured work per call is identical).
    static cudaStream_t s1 = nullptr;
    static cudaEvent_t e_fork, e_join;
    static cudaEvent_t e_feat[NCHUNK];
    if (!s1) {
        cudaStreamCreateWithFlags(&s1, cudaStreamNonBlocking);
        cudaEventCreateWithFlags(&e_fork, cudaEventDisableTiming);
        cudaEventCreateWithFlags(&e_join, cudaEventDisableTiming);
        for (int c = 0; c < NCHUNK; ++c)
            cudaEventCreateWithFlags(&e_feat[c], cudaEventDisableTiming);
    }

    static bool smem_set = false;
    if (!smem_set) {
        cudaFuncSetAttribute(gemm_mma_kernel,
                             cudaFuncAttributeMaxDynamicSharedMemorySize, GEMM_SMEM);
        smem_set = true;
    }

    cudaStream_t s0 = 0;   // capture-origin (legacy default) stream

    // Zero the atomic accumulation target, then fork s1 off s0.
    cudaMemsetAsync(out, 0, (size_t)Bsz * sizeof(float), s0);
    cudaEventRecord(e_fork, s0);
    cudaStreamWaitEvent(s1, e_fork, 0);

    // s1: W1 conversion (independent of features)
    w1_cvt_kernel<<<(H * K) / 256, 256, 0, s1>>>(W1, wh);

    // s0: feature chunks; s1: gemm chunks gated per-chunk.
    for (int c = 0; c < NCHUNK; ++c) {
        const size_t row0 = (size_t)c * BCH;
        feature_kernel<<<(BCH * D) / 256, 256, 0, s0>>>(
            emb + row0 * (S * D), w_long, w_mid, fh + row0 * K);
        cudaEventRecord(e_feat[c], s0);

        cudaStreamWaitEvent(s1, e_feat[c], 0);
        dim3 grid(BCH / 128, H / 128);   // (16, 8) = 128 CTAs
        gemm_mma_kernel<<<grid, GT, GEMM_SMEM, s1>>>(
            fh + row0 * K, wh, W2, out + row0);
    }

    // Join s1 back into s0 before returning.
    cudaEventRecord(e_join, s1);
    cudaStreamWaitEvent(s0, e_join, 0);
}